// round 5
// baseline (speedup 1.0000x reference)
#include <cuda_runtime.h>
#include <cuda_bf16.h>
#include <cstdint>

#define NNODES  100000
#define NEDGES  1600000
#define NGRAPHS 64
#define DIM     128
#define NCLS    10
#define SCAN_B  1024
#define NBLK    ((NNODES + SCAN_B - 1) / SCAN_B)   // 98
#define PB      136                                // smem pitch in bf16 (272B: conflict-free frags)

// ---------------- persistent device scratch (no allocations allowed) ----------------
__device__ int   g_idx64;
__device__ int   g_deg_out[NNODES];
__device__ int   g_deg_in[NNODES];
__device__ int   g_fill[NNODES];
__device__ int   g_rowptr[NNODES + 1];
__device__ int   g_csr[NEDGES];
__device__ int   g_bsum[NBLK];
__device__ int   g_boff[128];
__device__ __align__(16) float g_bufA[(size_t)NNODES * DIM];
__device__ __align__(16) float g_bufB[(size_t)NNODES * DIM];
__device__ float g_gsum[NGRAPHS * DIM];
__device__ int   g_gcnt[NGRAPHS];

// ---------------- helpers ----------------
__device__ __forceinline__ int ldidx(const void* p, int i, bool w64) {
    if (w64) return (int)__ldg(((const long long*)p) + i);
    return __ldg(((const int*)p) + i);
}

__device__ __forceinline__ void mma16816(float* c, const uint32_t* a, uint32_t b0, uint32_t b1) {
    asm volatile(
        "mma.sync.aligned.m16n8k16.row.col.f32.bf16.bf16.f32 "
        "{%0,%1,%2,%3}, {%4,%5,%6,%7}, {%8,%9}, {%0,%1,%2,%3};"
        : "+f"(c[0]), "+f"(c[1]), "+f"(c[2]), "+f"(c[3])
        : "r"(a[0]), "r"(a[1]), "r"(a[2]), "r"(a[3]), "r"(b0), "r"(b1));
}

// ---------------- 1. dtype detection ----------------
__global__ void k_detect(const void* src) {
    __shared__ int any_nonzero;
    if (threadIdx.x == 0) any_nonzero = 0;
    __syncthreads();
    const unsigned int* p = (const unsigned int*)src;
    unsigned int v = p[2 * threadIdx.x + 1];
    if (v != 0u) atomicOr(&any_nonzero, 1);
    __syncthreads();
    if (threadIdx.x == 0) g_idx64 = (any_nonzero == 0) ? 1 : 0;
}

// ---------------- 2. zero scratch ----------------
__global__ void k_zero() {
    int i = blockIdx.x * blockDim.x + threadIdx.x;
    int stride = gridDim.x * blockDim.x;
    for (int j = i; j < NNODES; j += stride) {
        g_deg_out[j] = 0;
        g_deg_in[j]  = 0;
    }
    for (int j = i; j < NGRAPHS * DIM; j += stride) g_gsum[j] = 0.0f;
    if (i < NGRAPHS) g_gcnt[i] = 0;
}

// ---------------- 3. degree + graph-count histograms ----------------
__global__ void k_degrees(const void* src, const void* dst, const void* gids) {
    bool w64 = (g_idx64 != 0);
    int i0 = blockIdx.x * blockDim.x + threadIdx.x;
    int stride = gridDim.x * blockDim.x;
    for (int i = i0; i < NEDGES; i += stride) {
        int s = ldidx(src, i, w64);
        int d = ldidx(dst, i, w64);
        atomicAdd(&g_deg_out[s], 1);
        atomicAdd(&g_deg_in[d], 1);
    }
    for (int i = i0; i < NNODES; i += stride) {
        int g = ldidx(gids, i, w64);
        atomicAdd(&g_gcnt[g], 1);
    }
}

// ---------------- 4-6. coalesced 3-phase exclusive scan ----------------
__global__ void __launch_bounds__(SCAN_B) k_scanA() {
    __shared__ int sh[SCAN_B];
    int tid = threadIdx.x;
    int i = blockIdx.x * SCAN_B + tid;
    int v = (i < NNODES) ? g_deg_in[i] : 0;
    sh[tid] = v;
    __syncthreads();
    for (int off = 1; off < SCAN_B; off <<= 1) {
        int t = (tid >= off) ? sh[tid - off] : 0;
        __syncthreads();
        sh[tid] += t;
        __syncthreads();
    }
    if (i < NNODES) g_rowptr[i] = sh[tid] - v;
    if (tid == SCAN_B - 1) g_bsum[blockIdx.x] = sh[tid];
}

__global__ void k_scanB() {
    __shared__ int sh[128];
    int tid = threadIdx.x;
    int v = (tid < NBLK) ? g_bsum[tid] : 0;
    sh[tid] = v;
    __syncthreads();
    for (int off = 1; off < 128; off <<= 1) {
        int t = (tid >= off) ? sh[tid - off] : 0;
        __syncthreads();
        sh[tid] += t;
        __syncthreads();
    }
    g_boff[tid] = sh[tid] - v;
}

__global__ void __launch_bounds__(SCAN_B) k_scanC() {
    int tid = threadIdx.x;
    int i = blockIdx.x * SCAN_B + tid;
    if (i < NNODES) {
        int r = g_rowptr[i] + g_boff[blockIdx.x];
        g_rowptr[i] = r;
        g_fill[i]   = r;
    }
    if (i == 0) g_rowptr[NNODES] = NEDGES;
}

// ---------------- 7. CSR scatter ----------------
__global__ void k_scatter(const void* src, const void* dst) {
    bool w64 = (g_idx64 != 0);
    int i0 = blockIdx.x * blockDim.x + threadIdx.x;
    int stride = gridDim.x * blockDim.x;
    for (int e = i0; e < NEDGES; e += stride) {
        int d = ldidx(dst, e, w64);
        int s = ldidx(src, e, w64);
        int pos = atomicAdd(&g_fill[d], 1);
        g_csr[pos] = s;
    }
}

// ---------------- 8. mma.sync split-bf16 GEMM ----------------
// C[M,128] = (LAYER==1 ? diag(rsqrt(deg_out)) : I) * A[M,128] @ W[128,128]
// D = Ahi*Bhi + Ahi*Blo + Alo*Bhi; fragments ld from smem, pitch PB=136 bf16.
#define SM_AHI 0
#define SM_ALO (128 * PB)
#define SM_BHI (2 * 128 * PB)
#define SM_BLO (3 * 128 * PB)
#define GEMM_DYN_SMEM (4 * 128 * PB * 2)   // 139264 bytes

template <int LAYER>
__global__ void __launch_bounds__(256) k_mmagemm(const float* __restrict__ Aext,
                                                 const float* __restrict__ W, int M) {
    extern __shared__ __align__(16) __nv_bfloat16 sm[];

    const float* __restrict__ A = (LAYER == 1) ? Aext : g_bufB;
    float* __restrict__ C = g_bufA;

    int tid = threadIdx.x;
    int wid = tid >> 5;       // 0..7
    int lane = tid & 31;
    int blockM = blockIdx.x * 128;

    // ---- stage A (128x128 f32 -> bf16 hi/lo), row-major pitch PB ----
#pragma unroll
    for (int it = 0; it < 16; it++) {
        int idx4 = tid + it * 256;           // 0..4095
        int row = idx4 >> 5;                 // 0..127
        int c4 = (idx4 & 31) * 4;            // 0..124
        int grow = blockM + row;
        float4 v = make_float4(0.f, 0.f, 0.f, 0.f);
        if (grow < M) {
            v = *(const float4*)(A + (long)grow * 128 + c4);
            if (LAYER == 1) {
                float sc = rsqrtf((float)max(g_deg_out[grow], 1));
                v.x *= sc; v.y *= sc; v.z *= sc; v.w *= sc;
            }
        }
        __nv_bfloat16 hx = __float2bfloat16(v.x), hy = __float2bfloat16(v.y);
        __nv_bfloat16 hz = __float2bfloat16(v.z), hw = __float2bfloat16(v.w);
        __nv_bfloat162 h0; h0.x = hx; h0.y = hy;
        __nv_bfloat162 h1; h1.x = hz; h1.y = hw;
        __nv_bfloat162 l0; l0.x = __float2bfloat16(v.x - __bfloat162float(hx));
        l0.y = __float2bfloat16(v.y - __bfloat162float(hy));
        __nv_bfloat162 l1; l1.x = __float2bfloat16(v.z - __bfloat162float(hz));
        l1.y = __float2bfloat16(v.w - __bfloat162float(hw));
        *(__nv_bfloat162*)(sm + SM_AHI + row * PB + c4)     = h0;
        *(__nv_bfloat162*)(sm + SM_AHI + row * PB + c4 + 2) = h1;
        *(__nv_bfloat162*)(sm + SM_ALO + row * PB + c4)     = l0;
        *(__nv_bfloat162*)(sm + SM_ALO + row * PB + c4 + 2) = l1;
    }
    // ---- stage W transposed: Bt[n][k] = W[k][n], bf16 hi/lo ----
#pragma unroll
    for (int it = 0; it < 16; it++) {
        int idx4 = tid + it * 256;
        int k = idx4 >> 5;
        int n4 = (idx4 & 31) * 4;
        float4 w = *(const float4*)(W + k * 128 + n4);
        float wv[4] = {w.x, w.y, w.z, w.w};
#pragma unroll
        for (int j = 0; j < 4; j++) {
            __nv_bfloat16 hi = __float2bfloat16(wv[j]);
            __nv_bfloat16 lo = __float2bfloat16(wv[j] - __bfloat162float(hi));
            sm[SM_BHI + (n4 + j) * PB + k] = hi;
            sm[SM_BLO + (n4 + j) * PB + k] = lo;
        }
    }
    __syncthreads();

    // ---- warp w: rows [16w, 16w+16), 16 n-tiles of 8 ----
    float acc[16][4];
#pragma unroll
    for (int nt = 0; nt < 16; nt++)
#pragma unroll
        for (int j = 0; j < 4; j++) acc[nt][j] = 0.0f;

    int r0 = wid * 16 + (lane >> 2);    // local row for a0/a2
    int q2 = (lane & 3) * 2;            // k sub-offset
    int nrow = lane >> 2;               // n within tile for B frags

#pragma unroll
    for (int ks = 0; ks < 8; ks++) {
        int kk = ks * 16;
        uint32_t ahi[4], alo[4];
        ahi[0] = *(const uint32_t*)(sm + SM_AHI + r0 * PB + kk + q2);
        ahi[1] = *(const uint32_t*)(sm + SM_AHI + (r0 + 8) * PB + kk + q2);
        ahi[2] = *(const uint32_t*)(sm + SM_AHI + r0 * PB + kk + q2 + 8);
        ahi[3] = *(const uint32_t*)(sm + SM_AHI + (r0 + 8) * PB + kk + q2 + 8);
        alo[0] = *(const uint32_t*)(sm + SM_ALO + r0 * PB + kk + q2);
        alo[1] = *(const uint32_t*)(sm + SM_ALO + (r0 + 8) * PB + kk + q2);
        alo[2] = *(const uint32_t*)(sm + SM_ALO + r0 * PB + kk + q2 + 8);
        alo[3] = *(const uint32_t*)(sm + SM_ALO + (r0 + 8) * PB + kk + q2 + 8);
#pragma unroll
        for (int nt = 0; nt < 16; nt++) {
            int bn = nt * 8 + nrow;
            uint32_t bh0 = *(const uint32_t*)(sm + SM_BHI + bn * PB + kk + q2);
            uint32_t bh1 = *(const uint32_t*)(sm + SM_BHI + bn * PB + kk + q2 + 8);
            uint32_t bl0 = *(const uint32_t*)(sm + SM_BLO + bn * PB + kk + q2);
            uint32_t bl1 = *(const uint32_t*)(sm + SM_BLO + bn * PB + kk + q2 + 8);
            mma16816(acc[nt], ahi, bh0, bh1);
            mma16816(acc[nt], ahi, bl0, bl1);
            mma16816(acc[nt], alo, bh0, bh1);
        }
    }

    // ---- epilogue: direct stores (c0,c1 adjacent cols -> float2) ----
    int growA = blockM + r0;
    int growB = growA + 8;
#pragma unroll
    for (int nt = 0; nt < 16; nt++) {
        int col = nt * 8 + q2;
        if (growA < M) *(float2*)(C + (long)growA * 128 + col) = make_float2(acc[nt][0], acc[nt][1]);
        if (growB < M) *(float2*)(C + (long)growB * 128 + col) = make_float2(acc[nt][2], acc[nt][3]);
    }
}

// ---------------- 9. SpMM (warp per dst row) ----------------
template <bool FINAL>
__global__ void __launch_bounds__(256) k_spmm(const float* __restrict__ bias,
                                              const void* __restrict__ gids) {
    int warp = (blockIdx.x * blockDim.x + threadIdx.x) >> 5;
    if (warp >= NNODES) return;
    int lane = threadIdx.x & 31;
    int beg = g_rowptr[warp], end = g_rowptr[warp + 1];
    const float* __restrict__ T = g_bufA;
    float4 acc0 = make_float4(0.f, 0.f, 0.f, 0.f);
    float4 acc1 = make_float4(0.f, 0.f, 0.f, 0.f);
    int e = beg;
    for (; e + 8 <= end; e += 8) {
        int s0 = g_csr[e],     s1 = g_csr[e + 1], s2 = g_csr[e + 2], s3 = g_csr[e + 3];
        int s4 = g_csr[e + 4], s5 = g_csr[e + 5], s6 = g_csr[e + 6], s7 = g_csr[e + 7];
        float4 v0 = __ldg((const float4*)(T + (long)s0 * 128 + lane * 4));
        float4 v1 = __ldg((const float4*)(T + (long)s1 * 128 + lane * 4));
        float4 v2 = __ldg((const float4*)(T + (long)s2 * 128 + lane * 4));
        float4 v3 = __ldg((const float4*)(T + (long)s3 * 128 + lane * 4));
        float4 v4 = __ldg((const float4*)(T + (long)s4 * 128 + lane * 4));
        float4 v5 = __ldg((const float4*)(T + (long)s5 * 128 + lane * 4));
        float4 v6 = __ldg((const float4*)(T + (long)s6 * 128 + lane * 4));
        float4 v7 = __ldg((const float4*)(T + (long)s7 * 128 + lane * 4));
        acc0.x += (v0.x + v1.x) + (v2.x + v3.x);
        acc0.y += (v0.y + v1.y) + (v2.y + v3.y);
        acc0.z += (v0.z + v1.z) + (v2.z + v3.z);
        acc0.w += (v0.w + v1.w) + (v2.w + v3.w);
        acc1.x += (v4.x + v5.x) + (v6.x + v7.x);
        acc1.y += (v4.y + v5.y) + (v6.y + v7.y);
        acc1.z += (v4.z + v5.z) + (v6.z + v7.z);
        acc1.w += (v4.w + v5.w) + (v6.w + v7.w);
    }
    for (; e + 4 <= end; e += 4) {
        int s0 = g_csr[e], s1 = g_csr[e + 1], s2 = g_csr[e + 2], s3 = g_csr[e + 3];
        float4 v0 = __ldg((const float4*)(T + (long)s0 * 128 + lane * 4));
        float4 v1 = __ldg((const float4*)(T + (long)s1 * 128 + lane * 4));
        float4 v2 = __ldg((const float4*)(T + (long)s2 * 128 + lane * 4));
        float4 v3 = __ldg((const float4*)(T + (long)s3 * 128 + lane * 4));
        acc0.x += (v0.x + v1.x) + (v2.x + v3.x);
        acc0.y += (v0.y + v1.y) + (v2.y + v3.y);
        acc0.z += (v0.z + v1.z) + (v2.z + v3.z);
        acc0.w += (v0.w + v1.w) + (v2.w + v3.w);
    }
    for (; e < end; e++) {
        int s = g_csr[e];
        float4 v = __ldg((const float4*)(T + (long)s * 128 + lane * 4));
        acc1.x += v.x; acc1.y += v.y; acc1.z += v.z; acc1.w += v.w;
    }
    float4 acc = make_float4(acc0.x + acc1.x, acc0.y + acc1.y,
                             acc0.z + acc1.z, acc0.w + acc1.w);
    float ri = rsqrtf((float)max(end - beg, 1));
    float4 b = *(const float4*)(bias + lane * 4);
    if (!FINAL) {
        float ro = rsqrtf((float)max(g_deg_out[warp], 1));
        float4 o;
        o.x = fmaxf(fmaf(acc.x, ri, b.x), 0.f) * ro;
        o.y = fmaxf(fmaf(acc.y, ri, b.y), 0.f) * ro;
        o.z = fmaxf(fmaf(acc.z, ri, b.z), 0.f) * ro;
        o.w = fmaxf(fmaf(acc.w, ri, b.w), 0.f) * ro;
        *(float4*)(g_bufB + (long)warp * 128 + lane * 4) = o;
    } else {
        float4 o;
        o.x = fmaxf(fmaf(acc.x, ri, b.x), 0.f);
        o.y = fmaxf(fmaf(acc.y, ri, b.y), 0.f);
        o.z = fmaxf(fmaf(acc.z, ri, b.z), 0.f);
        o.w = fmaxf(fmaf(acc.w, ri, b.w), 0.f);
        bool w64 = (g_idx64 != 0);
        int g = ldidx(gids, warp, w64);
        float* dstp = g_gsum + g * 128 + lane * 4;
        atomicAdd(dstp + 0, o.x);
        atomicAdd(dstp + 1, o.y);
        atomicAdd(dstp + 2, o.z);
        atomicAdd(dstp + 3, o.w);
    }
}

// ---------------- 10. classifier head ----------------
__global__ void k_final(const float* __restrict__ Wc, const float* __restrict__ bc,
                        float* __restrict__ out) {
    int t = threadIdx.x;
    if (t >= NGRAPHS * NCLS) return;
    int g = t / NCLS, c = t % NCLS;
    float s = 0.f;
#pragma unroll 8
    for (int k = 0; k < 128; k++) s = fmaf(g_gsum[g * 128 + k], Wc[k * NCLS + c], s);
    float cnt = (float)max(g_gcnt[g], 1);
    out[t] = s / cnt + bc[c];
}

// ---------------- launch ----------------
extern "C" void kernel_launch(void* const* d_in, const int* in_sizes, int n_in,
                              void* d_out, int out_size) {
    const float* h   = (const float*)d_in[0];
    const void*  src = d_in[1];
    const void*  dst = d_in[2];
    const void*  gid = d_in[3];
    const float* W1  = (const float*)d_in[4];
    const float* b1  = (const float*)d_in[5];
    const float* W2  = (const float*)d_in[6];
    const float* b2  = (const float*)d_in[7];
    const float* Wc  = (const float*)d_in[8];
    const float* bc  = (const float*)d_in[9];
    float* out = (float*)d_out;

    const int M = NNODES;
    int gemmGrid = (M + 127) / 128;
    int spmmGrid = (M * 32 + 255) / 256;

    cudaFuncSetAttribute(k_mmagemm<1>, cudaFuncAttributeMaxDynamicSharedMemorySize, GEMM_DYN_SMEM);
    cudaFuncSetAttribute(k_mmagemm<2>, cudaFuncAttributeMaxDynamicSharedMemorySize, GEMM_DYN_SMEM);

    k_detect<<<1, 256>>>(src);                                     // 1
    k_zero<<<512, 256>>>();                                        // 2
    k_degrees<<<1184, 256>>>(src, dst, gid);                       // 3
    k_mmagemm<1><<<gemmGrid, 256, GEMM_DYN_SMEM>>>(h, W1, M);      // 4  <- profiled slot
    k_scanA<<<NBLK, SCAN_B>>>();                                   // 5
    k_scanB<<<1, 128>>>();                                         // 6
    k_scanC<<<NBLK, SCAN_B>>>();                                   // 7
    k_scatter<<<1184, 256>>>(src, dst);                            // 8
    k_spmm<false><<<spmmGrid, 256>>>(b1, nullptr);                 // 9
    k_mmagemm<2><<<gemmGrid, 256, GEMM_DYN_SMEM>>>(nullptr, W2, M);// 10
    k_spmm<true><<<spmmGrid, 256>>>(b2, gid);                      // 11
    k_final<<<1, NGRAPHS * NCLS>>>(Wc, bc, out);                   // 12
}

// round 6
// speedup vs baseline: 1.0244x; 1.0244x over previous
#include <cuda_runtime.h>
#include <cuda_bf16.h>
#include <cstdint>

#define NNODES  100000
#define NEDGES  1600000
#define NGRAPHS 64
#define DIM     128
#define NCLS    10
#define SCAN_B  1024
#define NBLK    ((NNODES + SCAN_B - 1) / SCAN_B)   // 98
#define PB      136                                // smem pitch in bf16 (272B rows)

// ---------------- persistent device scratch ----------------
__device__ int   g_idx64;
__device__ int   g_deg_out[NNODES];
__device__ int   g_deg_in[NNODES];
__device__ int   g_fill[NNODES];
__device__ int   g_rowptr[NNODES + 1];
__device__ int   g_csr[NEDGES];
__device__ int   g_bsum[NBLK];
__device__ int   g_boff[128];
__device__ __align__(16) float g_bufA[(size_t)NNODES * DIM];
__device__ __align__(16) float g_bufB[(size_t)NNODES * DIM];
__device__ float g_gsum[NGRAPHS * DIM];
__device__ int   g_gcnt[NGRAPHS];

// ---------------- helpers ----------------
__device__ __forceinline__ int ldidx(const void* p, int i, bool w64) {
    if (w64) return (int)__ldg(((const long long*)p) + i);
    return __ldg(((const int*)p) + i);
}

__device__ __forceinline__ void mma16816(float* c, const uint32_t* a, uint32_t b0, uint32_t b1) {
    asm volatile(
        "mma.sync.aligned.m16n8k16.row.col.f32.bf16.bf16.f32 "
        "{%0,%1,%2,%3}, {%4,%5,%6,%7}, {%8,%9}, {%0,%1,%2,%3};"
        : "+f"(c[0]), "+f"(c[1]), "+f"(c[2]), "+f"(c[3])
        : "r"(a[0]), "r"(a[1]), "r"(a[2]), "r"(a[3]), "r"(b0), "r"(b1));
}

__device__ __forceinline__ void ldm_x4(uint32_t* r, uint32_t saddr) {
    asm volatile("ldmatrix.sync.aligned.m8n8.x4.shared.b16 {%0,%1,%2,%3}, [%4];"
                 : "=r"(r[0]), "=r"(r[1]), "=r"(r[2]), "=r"(r[3]) : "r"(saddr));
}

__device__ __forceinline__ uint32_t smem_u32(const void* p) {
    uint32_t a;
    asm("{ .reg .u64 t; cvta.to.shared.u64 t, %1; cvt.u32.u64 %0, t; }" : "=r"(a) : "l"(p));
    return a;
}

// ---------------- 1. dtype detection ----------------
__global__ void k_detect(const void* src) {
    __shared__ int any_nonzero;
    if (threadIdx.x == 0) any_nonzero = 0;
    __syncthreads();
    const unsigned int* p = (const unsigned int*)src;
    unsigned int v = p[2 * threadIdx.x + 1];
    if (v != 0u) atomicOr(&any_nonzero, 1);
    __syncthreads();
    if (threadIdx.x == 0) g_idx64 = (any_nonzero == 0) ? 1 : 0;
}

// ---------------- 2. zero scratch ----------------
__global__ void k_zero() {
    int i = blockIdx.x * blockDim.x + threadIdx.x;
    int stride = gridDim.x * blockDim.x;
    for (int j = i; j < NNODES; j += stride) {
        g_deg_out[j] = 0;
        g_deg_in[j]  = 0;
    }
    for (int j = i; j < NGRAPHS * DIM; j += stride) g_gsum[j] = 0.0f;
    if (i < NGRAPHS) g_gcnt[i] = 0;
}

// ---------------- 3. degree + graph-count histograms ----------------
__global__ void k_degrees(const void* src, const void* dst, const void* gids) {
    bool w64 = (g_idx64 != 0);
    int i0 = blockIdx.x * blockDim.x + threadIdx.x;
    int stride = gridDim.x * blockDim.x;
    for (int i = i0; i < NEDGES; i += stride) {
        int s = ldidx(src, i, w64);
        int d = ldidx(dst, i, w64);
        atomicAdd(&g_deg_out[s], 1);
        atomicAdd(&g_deg_in[d], 1);
    }
    for (int i = i0; i < NNODES; i += stride) {
        int g = ldidx(gids, i, w64);
        atomicAdd(&g_gcnt[g], 1);
    }
}

// ---------------- 4-6. coalesced 3-phase exclusive scan ----------------
__global__ void __launch_bounds__(SCAN_B) k_scanA() {
    __shared__ int sh[SCAN_B];
    int tid = threadIdx.x;
    int i = blockIdx.x * SCAN_B + tid;
    int v = (i < NNODES) ? g_deg_in[i] : 0;
    sh[tid] = v;
    __syncthreads();
    for (int off = 1; off < SCAN_B; off <<= 1) {
        int t = (tid >= off) ? sh[tid - off] : 0;
        __syncthreads();
        sh[tid] += t;
        __syncthreads();
    }
    if (i < NNODES) g_rowptr[i] = sh[tid] - v;
    if (tid == SCAN_B - 1) g_bsum[blockIdx.x] = sh[tid];
}

__global__ void k_scanB() {
    __shared__ int sh[128];
    int tid = threadIdx.x;
    int v = (tid < NBLK) ? g_bsum[tid] : 0;
    sh[tid] = v;
    __syncthreads();
    for (int off = 1; off < 128; off <<= 1) {
        int t = (tid >= off) ? sh[tid - off] : 0;
        __syncthreads();
        sh[tid] += t;
        __syncthreads();
    }
    g_boff[tid] = sh[tid] - v;
}

__global__ void __launch_bounds__(SCAN_B) k_scanC() {
    int tid = threadIdx.x;
    int i = blockIdx.x * SCAN_B + tid;
    if (i < NNODES) {
        int r = g_rowptr[i] + g_boff[blockIdx.x];
        g_rowptr[i] = r;
        g_fill[i]   = r;
    }
    if (i == 0) g_rowptr[NNODES] = NEDGES;
}

// ---------------- 7. CSR scatter ----------------
__global__ void k_scatter(const void* src, const void* dst) {
    bool w64 = (g_idx64 != 0);
    int i0 = blockIdx.x * blockDim.x + threadIdx.x;
    int stride = gridDim.x * blockDim.x;
    for (int e = i0; e < NEDGES; e += stride) {
        int d = ldidx(dst, e, w64);
        int s = ldidx(src, e, w64);
        int pos = atomicAdd(&g_fill[d], 1);
        g_csr[pos] = s;
    }
}

// ---------------- 8. mma.sync split-bf16 GEMM (ldmatrix, 512 threads) ----------------
// C[M,128] = (LAYER==1 ? diag(rsqrt(deg_out)) : I) * A[M,128] @ W[128,128]
// D = Ahi*Bhi + Ahi*Blo + Alo*Bhi. Warp w: rows [16*(w/2),+16), cols [64*(w&1),+64).
#define SM_AHI 0
#define SM_ALO (128 * PB)
#define SM_BHI (2 * 128 * PB)
#define SM_BLO (3 * 128 * PB)
#define GEMM_DYN_SMEM (4 * 128 * PB * 2)   // 139264 bytes

template <int LAYER>
__global__ void __launch_bounds__(512) k_mmagemm(const float* __restrict__ Aext,
                                                 const float* __restrict__ W, int M) {
    extern __shared__ __align__(16) __nv_bfloat16 sm[];

    const float* __restrict__ A = (LAYER == 1) ? Aext : g_bufB;
    float* __restrict__ C = g_bufA;

    int tid = threadIdx.x;
    int wid = tid >> 5;       // 0..15
    int lane = tid & 31;
    int blockM = blockIdx.x * 128;

    // ---- stage A (128x128 f32 -> bf16 hi/lo) ----
#pragma unroll
    for (int it = 0; it < 8; it++) {
        int idx4 = tid + it * 512;           // 0..4095
        int row = idx4 >> 5;                 // 0..127
        int c4 = (idx4 & 31) * 4;
        int grow = blockM + row;
        float4 v = make_float4(0.f, 0.f, 0.f, 0.f);
        if (grow < M) {
            v = *(const float4*)(A + (long)grow * 128 + c4);
            if (LAYER == 1) {
                float sc = rsqrtf((float)max(g_deg_out[grow], 1));
                v.x *= sc; v.y *= sc; v.z *= sc; v.w *= sc;
            }
        }
        __nv_bfloat16 hx = __float2bfloat16(v.x), hy = __float2bfloat16(v.y);
        __nv_bfloat16 hz = __float2bfloat16(v.z), hw = __float2bfloat16(v.w);
        __nv_bfloat162 h0; h0.x = hx; h0.y = hy;
        __nv_bfloat162 h1; h1.x = hz; h1.y = hw;
        __nv_bfloat162 l0; l0.x = __float2bfloat16(v.x - __bfloat162float(hx));
        l0.y = __float2bfloat16(v.y - __bfloat162float(hy));
        __nv_bfloat162 l1; l1.x = __float2bfloat16(v.z - __bfloat162float(hz));
        l1.y = __float2bfloat16(v.w - __bfloat162float(hw));
        *(__nv_bfloat162*)(sm + SM_AHI + row * PB + c4)     = h0;
        *(__nv_bfloat162*)(sm + SM_AHI + row * PB + c4 + 2) = h1;
        *(__nv_bfloat162*)(sm + SM_ALO + row * PB + c4)     = l0;
        *(__nv_bfloat162*)(sm + SM_ALO + row * PB + c4 + 2) = l1;
    }
    // ---- stage W transposed: Bt[n][k] = W[k][n], bf16 hi/lo ----
#pragma unroll
    for (int it = 0; it < 8; it++) {
        int idx4 = tid + it * 512;
        int k = idx4 >> 5;
        int n4 = (idx4 & 31) * 4;
        float4 w = *(const float4*)(W + k * 128 + n4);
        float wv[4] = {w.x, w.y, w.z, w.w};
#pragma unroll
        for (int j = 0; j < 4; j++) {
            __nv_bfloat16 hi = __float2bfloat16(wv[j]);
            __nv_bfloat16 lo = __float2bfloat16(wv[j] - __bfloat162float(hi));
            sm[SM_BHI + (n4 + j) * PB + k] = hi;
            sm[SM_BLO + (n4 + j) * PB + k] = lo;
        }
    }
    __syncthreads();

    // ---- compute: warp w -> rows [16*(w>>1), +16), cols [64*(w&1), +64) ----
    float acc[8][4];
#pragma unroll
    for (int nt = 0; nt < 8; nt++)
#pragma unroll
        for (int j = 0; j < 4; j++) acc[nt][j] = 0.0f;

    int warpRow = (wid >> 1) * 16;
    int warpCol = (wid & 1) * 64;
    int mtx  = lane >> 3;       // 0..3 matrix index for ldmatrix
    int lrow = lane & 7;

    uint32_t smbase = smem_u32(sm);
    // A frag address (same pattern for hi/lo): row = warpRow + lrow + (mtx&1)*8, col = kk + (mtx>>1)*8
    uint32_t aoffElem = (uint32_t)((warpRow + lrow + (mtx & 1) * 8) * PB + (mtx >> 1) * 8);
    // B frag address: for nt-pair base nb: n = nb + (mtx>>1)*8 + lrow, col = kk + (mtx&1)*8
    uint32_t boffRow  = (uint32_t)((warpCol + (mtx >> 1) * 8 + lrow) * PB + (mtx & 1) * 8);

#pragma unroll
    for (int ks = 0; ks < 8; ks++) {
        int kk = ks * 16;
        uint32_t ahi[4], alo[4];
        ldm_x4(ahi, smbase + (SM_AHI + aoffElem + kk) * 2);
        ldm_x4(alo, smbase + (SM_ALO + aoffElem + kk) * 2);
#pragma unroll
        for (int np = 0; np < 4; np++) {       // nt pair: tiles 2np, 2np+1
            uint32_t bhi[4], blo[4];
            uint32_t bo = boffRow + (uint32_t)(np * 16 * PB + kk);
            ldm_x4(bhi, smbase + (SM_BHI + bo) * 2);
            ldm_x4(blo, smbase + (SM_BLO + bo) * 2);
            mma16816(acc[2 * np],     ahi, bhi[0], bhi[1]);
            mma16816(acc[2 * np],     ahi, blo[0], blo[1]);
            mma16816(acc[2 * np],     alo, bhi[0], bhi[1]);
            mma16816(acc[2 * np + 1], ahi, bhi[2], bhi[3]);
            mma16816(acc[2 * np + 1], ahi, blo[2], blo[3]);
            mma16816(acc[2 * np + 1], alo, bhi[2], bhi[3]);
        }
    }

    // ---- epilogue: direct float2 stores ----
    int r0 = warpRow + (lane >> 2);
    int q2 = (lane & 3) * 2;
    int growA = blockM + r0;
    int growB = growA + 8;
#pragma unroll
    for (int nt = 0; nt < 8; nt++) {
        int col = warpCol + nt * 8 + q2;
        if (growA < M) *(float2*)(C + (long)growA * 128 + col) = make_float2(acc[nt][0], acc[nt][1]);
        if (growB < M) *(float2*)(C + (long)growB * 128 + col) = make_float2(acc[nt][2], acc[nt][3]);
    }
}

// ---------------- 9. SpMM (warp per dst row) ----------------
template <bool FINAL>
__global__ void __launch_bounds__(256) k_spmm(const float* __restrict__ bias,
                                              const void* __restrict__ gids) {
    int warp = (blockIdx.x * blockDim.x + threadIdx.x) >> 5;
    if (warp >= NNODES) return;
    int lane = threadIdx.x & 31;
    int beg = g_rowptr[warp], end = g_rowptr[warp + 1];
    const float* __restrict__ T = g_bufA;
    float4 acc0 = make_float4(0.f, 0.f, 0.f, 0.f);
    float4 acc1 = make_float4(0.f, 0.f, 0.f, 0.f);
    int e = beg;
    for (; e + 8 <= end; e += 8) {
        int s0 = g_csr[e],     s1 = g_csr[e + 1], s2 = g_csr[e + 2], s3 = g_csr[e + 3];
        int s4 = g_csr[e + 4], s5 = g_csr[e + 5], s6 = g_csr[e + 6], s7 = g_csr[e + 7];
        float4 v0 = __ldg((const float4*)(T + (long)s0 * 128 + lane * 4));
        float4 v1 = __ldg((const float4*)(T + (long)s1 * 128 + lane * 4));
        float4 v2 = __ldg((const float4*)(T + (long)s2 * 128 + lane * 4));
        float4 v3 = __ldg((const float4*)(T + (long)s3 * 128 + lane * 4));
        float4 v4 = __ldg((const float4*)(T + (long)s4 * 128 + lane * 4));
        float4 v5 = __ldg((const float4*)(T + (long)s5 * 128 + lane * 4));
        float4 v6 = __ldg((const float4*)(T + (long)s6 * 128 + lane * 4));
        float4 v7 = __ldg((const float4*)(T + (long)s7 * 128 + lane * 4));
        acc0.x += (v0.x + v1.x) + (v2.x + v3.x);
        acc0.y += (v0.y + v1.y) + (v2.y + v3.y);
        acc0.z += (v0.z + v1.z) + (v2.z + v3.z);
        acc0.w += (v0.w + v1.w) + (v2.w + v3.w);
        acc1.x += (v4.x + v5.x) + (v6.x + v7.x);
        acc1.y += (v4.y + v5.y) + (v6.y + v7.y);
        acc1.z += (v4.z + v5.z) + (v6.z + v7.z);
        acc1.w += (v4.w + v5.w) + (v6.w + v7.w);
    }
    for (; e + 4 <= end; e += 4) {
        int s0 = g_csr[e], s1 = g_csr[e + 1], s2 = g_csr[e + 2], s3 = g_csr[e + 3];
        float4 v0 = __ldg((const float4*)(T + (long)s0 * 128 + lane * 4));
        float4 v1 = __ldg((const float4*)(T + (long)s1 * 128 + lane * 4));
        float4 v2 = __ldg((const float4*)(T + (long)s2 * 128 + lane * 4));
        float4 v3 = __ldg((const float4*)(T + (long)s3 * 128 + lane * 4));
        acc0.x += (v0.x + v1.x) + (v2.x + v3.x);
        acc0.y += (v0.y + v1.y) + (v2.y + v3.y);
        acc0.z += (v0.z + v1.z) + (v2.z + v3.z);
        acc0.w += (v0.w + v1.w) + (v2.w + v3.w);
    }
    for (; e < end; e++) {
        int s = g_csr[e];
        float4 v = __ldg((const float4*)(T + (long)s * 128 + lane * 4));
        acc1.x += v.x; acc1.y += v.y; acc1.z += v.z; acc1.w += v.w;
    }
    float4 acc = make_float4(acc0.x + acc1.x, acc0.y + acc1.y,
                             acc0.z + acc1.z, acc0.w + acc1.w);
    float ri = rsqrtf((float)max(end - beg, 1));
    float4 b = *(const float4*)(bias + lane * 4);
    if (!FINAL) {
        float ro = rsqrtf((float)max(g_deg_out[warp], 1));
        float4 o;
        o.x = fmaxf(fmaf(acc.x, ri, b.x), 0.f) * ro;
        o.y = fmaxf(fmaf(acc.y, ri, b.y), 0.f) * ro;
        o.z = fmaxf(fmaf(acc.z, ri, b.z), 0.f) * ro;
        o.w = fmaxf(fmaf(acc.w, ri, b.w), 0.f) * ro;
        *(float4*)(g_bufB + (long)warp * 128 + lane * 4) = o;
    } else {
        float4 o;
        o.x = fmaxf(fmaf(acc.x, ri, b.x), 0.f);
        o.y = fmaxf(fmaf(acc.y, ri, b.y), 0.f);
        o.z = fmaxf(fmaf(acc.z, ri, b.z), 0.f);
        o.w = fmaxf(fmaf(acc.w, ri, b.w), 0.f);
        bool w64 = (g_idx64 != 0);
        int g = ldidx(gids, warp, w64);
        float* dstp = g_gsum + g * 128 + lane * 4;
        atomicAdd(dstp + 0, o.x);
        atomicAdd(dstp + 1, o.y);
        atomicAdd(dstp + 2, o.z);
        atomicAdd(dstp + 3, o.w);
    }
}

// ---------------- 10. classifier head ----------------
__global__ void k_final(const float* __restrict__ Wc, const float* __restrict__ bc,
                        float* __restrict__ out) {
    int t = threadIdx.x;
    if (t >= NGRAPHS * NCLS) return;
    int g = t / NCLS, c = t % NCLS;
    float s = 0.f;
#pragma unroll 8
    for (int k = 0; k < 128; k++) s = fmaf(g_gsum[g * 128 + k], Wc[k * NCLS + c], s);
    float cnt = (float)max(g_gcnt[g], 1);
    out[t] = s / cnt + bc[c];
}

// ---------------- launch ----------------
extern "C" void kernel_launch(void* const* d_in, const int* in_sizes, int n_in,
                              void* d_out, int out_size) {
    const float* h   = (const float*)d_in[0];
    const void*  src = d_in[1];
    const void*  dst = d_in[2];
    const void*  gid = d_in[3];
    const float* W1  = (const float*)d_in[4];
    const float* b1  = (const float*)d_in[5];
    const float* W2  = (const float*)d_in[6];
    const float* b2  = (const float*)d_in[7];
    const float* Wc  = (const float*)d_in[8];
    const float* bc  = (const float*)d_in[9];
    float* out = (float*)d_out;

    const int M = NNODES;
    int gemmGrid = (M + 127) / 128;
    int spmmGrid = (M * 32 + 255) / 256;

    cudaFuncSetAttribute(k_mmagemm<1>, cudaFuncAttributeMaxDynamicSharedMemorySize, GEMM_DYN_SMEM);
    cudaFuncSetAttribute(k_mmagemm<2>, cudaFuncAttributeMaxDynamicSharedMemorySize, GEMM_DYN_SMEM);

    k_detect<<<1, 256>>>(src);                                     // 1
    k_zero<<<512, 256>>>();                                        // 2
    k_degrees<<<1184, 256>>>(src, dst, gid);                       // 3
    k_mmagemm<1><<<gemmGrid, 512, GEMM_DYN_SMEM>>>(h, W1, M);      // 4  <- profiled slot
    k_scanA<<<NBLK, SCAN_B>>>();                                   // 5
    k_scanB<<<1, 128>>>();                                         // 6
    k_scanC<<<NBLK, SCAN_B>>>();                                   // 7
    k_scatter<<<1184, 256>>>(src, dst);                            // 8
    k_spmm<false><<<spmmGrid, 256>>>(b1, nullptr);                 // 9
    k_mmagemm<2><<<gemmGrid, 512, GEMM_DYN_SMEM>>>(nullptr, W2, M);// 10
    k_spmm<true><<<spmmGrid, 256>>>(b2, gid);                      // 11
    k_final<<<1, NGRAPHS * NCLS>>>(Wc, bc, out);                   // 12
}